// round 2
// baseline (speedup 1.0000x reference)
#include <cuda_runtime.h>

// Problem constants (fixed by the dataset)
#define B_    8
#define F_    256
#define K_    64
#define ED_   256
#define TP_   4
#define WSZ_  16
#define L_    64       // TP*WSZ tokens per window
#define NWIN_ 256      // f*nW = 64*4

// Scratch: per-window adjacency A = deg @ edge  (256 * 64 * 64 floats = 4 MiB)
__device__ float g_A[NWIN_ * L_ * L_];

// ---------------------------------------------------------------------------
// Kernel A: A_w = deg_w @ edge_w for each of 256 windows (64x64x64 each)
// ---------------------------------------------------------------------------
__global__ void __launch_bounds__(256)
compute_A_kernel(const float* __restrict__ edge, const float* __restrict__ deg) {
    __shared__ float dg[L_ * L_];
    __shared__ float eg[L_ * L_];
    const int w = blockIdx.x;
    for (int i = threadIdx.x; i < L_ * L_; i += 256) {
        dg[i] = deg[w * L_ * L_ + i];
        eg[i] = edge[w * L_ * L_ + i];
    }
    __syncthreads();
    const int p  = threadIdx.x >> 2;          // row 0..63
    const int q0 = (threadIdx.x & 3) * 16;    // col block
    float acc[16];
#pragma unroll
    for (int j = 0; j < 16; j++) acc[j] = 0.f;
    for (int k = 0; k < L_; k++) {
        const float a = dg[p * L_ + k];
#pragma unroll
        for (int j = 0; j < 16; j++)
            acc[j] = fmaf(a, eg[k * L_ + q0 + j], acc[j]);
    }
#pragma unroll
    for (int j = 0; j < 16; j++)
        g_A[w * L_ * L_ + p * L_ + q0 + j] = acc[j];
}

// ---------------------------------------------------------------------------
// Kernel B: one CTA per (window, batch).
//   Phase 1: load 64x256 window, LayerNorm -> xn_s (smem)
//   Phase 2: y = xn @ Wp^T + bp   (64x256 @ 256x256), 8x8 register tiles
//   Phase 3: z = A_w @ y          (64x64  @ 64x256)
//   Phase 4: window-reverse store
// smem: xn/y [64][256] (reused), Wp tile [16][256], A [64][64], consts
// ---------------------------------------------------------------------------
__global__ void __launch_bounds__(256, 2)
window_kernel(const float* __restrict__ x,
              const float* __restrict__ gamma,
              const float* __restrict__ beta,
              const float* __restrict__ Wp,
              const float* __restrict__ bp,
              float* __restrict__ out) {
    extern __shared__ float sm[];
    float* xn_s    = sm;                       // 64*256 = 16384 (reused as y)
    float* Wp_s    = xn_s + 64 * 256;          // 16*256 = 4096
    float* A_s     = Wp_s + 16 * 256;          // 64*64  = 4096
    float* gamma_s = A_s + 64 * 64;            // 256
    float* beta_s  = gamma_s + 256;            // 256
    float* bp_s    = beta_s + 256;             // 256

    const int tid  = threadIdx.x;
    const int w    = blockIdx.x;               // 0..255 = fi*4 + wi
    const int b    = blockIdx.y;               // 0..7
    const int fi   = w >> 2;
    const int wi   = w & 3;
    const int lane = tid & 31;
    const int warp = tid >> 5;

    // Stage constants + A_w
    gamma_s[tid] = gamma[tid];
    beta_s[tid]  = beta[tid];
    bp_s[tid]    = bp[tid];
    {
        const float* Aw = g_A + (size_t)w * 4096;
        for (int i = tid; i < 4096; i += 256) A_s[i] = Aw[i];
    }

    // -------- Phase 1: LayerNorm. warp handles tokens {warp + 8*r} ---------
    for (int r = 0; r < 8; r++) {
        const int t  = warp + r * 8;           // 0..63
        const int tp = t >> 4, ws = t & 15;
        const float* xr = x + ((((size_t)b * 256 + fi * 4 + tp) * 64) + wi * 16 + ws) * 256;
        const float4 v0 = *(const float4*)(xr + lane * 4);
        const float4 v1 = *(const float4*)(xr + 128 + lane * 4);
        float s  = v0.x + v0.y + v0.z + v0.w + v1.x + v1.y + v1.z + v1.w;
        float s2 = v0.x*v0.x + v0.y*v0.y + v0.z*v0.z + v0.w*v0.w
                 + v1.x*v1.x + v1.y*v1.y + v1.z*v1.z + v1.w*v1.w;
#pragma unroll
        for (int o = 16; o > 0; o >>= 1) {
            s  += __shfl_xor_sync(0xFFFFFFFFu, s,  o);
            s2 += __shfl_xor_sync(0xFFFFFFFFu, s2, o);
        }
        const float mean = s * (1.f / 256.f);
        const float var  = s2 * (1.f / 256.f) - mean * mean;
        const float rstd = rsqrtf(var + 1e-5f);

        const int c0 = lane * 4;
        float4 g0 = *(const float4*)&gamma_s[c0];
        float4 b0 = *(const float4*)&beta_s[c0];
        float4 g1 = *(const float4*)&gamma_s[128 + c0];
        float4 b1 = *(const float4*)&beta_s[128 + c0];
        float4 n0, n1;
        n0.x = (v0.x - mean) * rstd * g0.x + b0.x;
        n0.y = (v0.y - mean) * rstd * g0.y + b0.y;
        n0.z = (v0.z - mean) * rstd * g0.z + b0.z;
        n0.w = (v0.w - mean) * rstd * g0.w + b0.w;
        n1.x = (v1.x - mean) * rstd * g1.x + b1.x;
        n1.y = (v1.y - mean) * rstd * g1.y + b1.y;
        n1.z = (v1.z - mean) * rstd * g1.z + b1.z;
        n1.w = (v1.w - mean) * rstd * g1.w + b1.w;
        *(float4*)&xn_s[t * 256 + c0]       = n0;
        *(float4*)&xn_s[t * 256 + 128 + c0] = n1;
    }

    // -------- Phase 2: y = xn @ Wp^T  (8x8 register tile per thread) -------
    // thread (ty=warp, tx=lane): tokens p = ty*8..ty*8+7,
    // channels c in {tx*4..tx*4+3} U {128+tx*4..128+tx*4+3}
    const int ty = warp;
    const int tx = lane;
    float acc[8][8];
#pragma unroll
    for (int i = 0; i < 8; i++)
#pragma unroll
        for (int j = 0; j < 8; j++) acc[i][j] = 0.f;

#pragma unroll 1
    for (int kb = 0; kb < 16; kb++) {
        __syncthreads();  // protect Wp_s from previous iter readers (and xn_s writes on kb=0)
        // stage Wp_s[kk][o] = Wp[o, kb*16+kk]; thread owns row o = tid
        {
            const float* wr = Wp + (size_t)tid * 256 + kb * 16;
            const float4 q0 = *(const float4*)(wr);
            const float4 q1 = *(const float4*)(wr + 4);
            const float4 q2 = *(const float4*)(wr + 8);
            const float4 q3 = *(const float4*)(wr + 12);
            Wp_s[ 0 * 256 + tid] = q0.x;  Wp_s[ 1 * 256 + tid] = q0.y;
            Wp_s[ 2 * 256 + tid] = q0.z;  Wp_s[ 3 * 256 + tid] = q0.w;
            Wp_s[ 4 * 256 + tid] = q1.x;  Wp_s[ 5 * 256 + tid] = q1.y;
            Wp_s[ 6 * 256 + tid] = q1.z;  Wp_s[ 7 * 256 + tid] = q1.w;
            Wp_s[ 8 * 256 + tid] = q2.x;  Wp_s[ 9 * 256 + tid] = q2.y;
            Wp_s[10 * 256 + tid] = q2.z;  Wp_s[11 * 256 + tid] = q2.w;
            Wp_s[12 * 256 + tid] = q3.x;  Wp_s[13 * 256 + tid] = q3.y;
            Wp_s[14 * 256 + tid] = q3.z;  Wp_s[15 * 256 + tid] = q3.w;
        }
        __syncthreads();
#pragma unroll
        for (int kk = 0; kk < 16; kk++) {
            float a[8];
#pragma unroll
            for (int i = 0; i < 8; i++)
                a[i] = xn_s[(ty * 8 + i) * 256 + kb * 16 + kk];  // warp-broadcast
            const float4 w0 = *(const float4*)&Wp_s[kk * 256 + tx * 4];
            const float4 w1 = *(const float4*)&Wp_s[kk * 256 + 128 + tx * 4];
            const float bb[8] = {w0.x, w0.y, w0.z, w0.w, w1.x, w1.y, w1.z, w1.w};
#pragma unroll
            for (int i = 0; i < 8; i++)
#pragma unroll
                for (int j = 0; j < 8; j++)
                    acc[i][j] = fmaf(a[i], bb[j], acc[i][j]);
        }
    }

    __syncthreads();  // all xn_s reads done; safe to overwrite with y
    // bias add + store y into xn_s (reuse)
#pragma unroll
    for (int i = 0; i < 8; i++) {
        const int t = ty * 8 + i;
        float4 y0, y1;
        y0.x = acc[i][0] + bp_s[tx * 4 + 0];
        y0.y = acc[i][1] + bp_s[tx * 4 + 1];
        y0.z = acc[i][2] + bp_s[tx * 4 + 2];
        y0.w = acc[i][3] + bp_s[tx * 4 + 3];
        y1.x = acc[i][4] + bp_s[128 + tx * 4 + 0];
        y1.y = acc[i][5] + bp_s[128 + tx * 4 + 1];
        y1.z = acc[i][6] + bp_s[128 + tx * 4 + 2];
        y1.w = acc[i][7] + bp_s[128 + tx * 4 + 3];
        *(float4*)&xn_s[t * 256 + tx * 4]       = y0;
        *(float4*)&xn_s[t * 256 + 128 + tx * 4] = y1;
    }
    __syncthreads();

    // -------- Phase 3: z = A @ y -------------------------------------------
#pragma unroll
    for (int i = 0; i < 8; i++)
#pragma unroll
        for (int j = 0; j < 8; j++) acc[i][j] = 0.f;

#pragma unroll 8
    for (int q = 0; q < 64; q++) {
        float a[8];
#pragma unroll
        for (int i = 0; i < 8; i++)
            a[i] = A_s[(ty * 8 + i) * 64 + q];                  // warp-broadcast
        const float4 w0 = *(const float4*)&xn_s[q * 256 + tx * 4];
        const float4 w1 = *(const float4*)&xn_s[q * 256 + 128 + tx * 4];
        const float bb[8] = {w0.x, w0.y, w0.z, w0.w, w1.x, w1.y, w1.z, w1.w};
#pragma unroll
        for (int i = 0; i < 8; i++)
#pragma unroll
            for (int j = 0; j < 8; j++)
                acc[i][j] = fmaf(a[i], bb[j], acc[i][j]);
    }

    // -------- Phase 4: window-reverse store --------------------------------
#pragma unroll
    for (int i = 0; i < 8; i++) {
        const int t  = ty * 8 + i;
        const int tp = t >> 4, ws = t & 15;
        float* orow = out + ((((size_t)b * 256 + fi * 4 + tp) * 64) + wi * 16 + ws) * 256;
        float4 z0, z1;
        z0.x = acc[i][0]; z0.y = acc[i][1]; z0.z = acc[i][2]; z0.w = acc[i][3];
        z1.x = acc[i][4]; z1.y = acc[i][5]; z1.z = acc[i][6]; z1.w = acc[i][7];
        *(float4*)(orow + tx * 4)       = z0;
        *(float4*)(orow + 128 + tx * 4) = z1;
    }
}

// ---------------------------------------------------------------------------
extern "C" void kernel_launch(void* const* d_in, const int* in_sizes, int n_in,
                              void* d_out, int out_size) {
    (void)in_sizes; (void)n_in; (void)out_size;
    const float* x     = (const float*)d_in[0];
    const float* gamma = (const float*)d_in[1];
    const float* beta  = (const float*)d_in[2];
    const float* Wp    = (const float*)d_in[3];
    const float* bp    = (const float*)d_in[4];
    const float* edge  = (const float*)d_in[5];
    const float* deg   = (const float*)d_in[6];
    float* out = (float*)d_out;

    compute_A_kernel<<<NWIN_, 256>>>(edge, deg);

    const int smem = (64 * 256 + 16 * 256 + 64 * 64 + 3 * 256) * (int)sizeof(float); // 101376 B
    cudaFuncSetAttribute(window_kernel, cudaFuncAttributeMaxDynamicSharedMemorySize, smem);
    window_kernel<<<dim3(NWIN_, B_), 256, smem>>>(x, gamma, beta, Wp, bp, out);
}

// round 9
// speedup vs baseline: 1.8735x; 1.8735x over previous
#include <cuda_runtime.h>
#include <cuda_bf16.h>
#include <cstdint>

// ---------------------------------------------------------------- constants
#define B_     8
#define L_     64
#define NWIN_  256

// padded strides (bytes). stride/4 mod 32 == 4  -> bank = 4*row + j, conflict-free
#define XN_STRIDE  144   // 72 bf16 per row (64 used)
#define A_STRIDE   144
#define WP_STRIDE  144
#define T_STRIDE   528   // 264 bf16 per row (256 used)

// smem layout (bytes)
#define T_HI    0        // 64*528   = 33792
#define T_LO    33792
#define XN_HI   67584    // 256*144  = 36864
#define XN_LO   104448
#define A_HI    141312   // 64*144   = 9216
#define A_LO    150528
#define BUF0    67584    // Wp chunk buf0 (hi@+0, lo@+36864) -- reuses XN after GEMM1
#define BUF1    141312   // reuses A region after GEMM1
#define WP_PLANE 36864
#define SMALL   215040   // mu @+0 (256B), rs @+256 (256B)
#define SMEM_TOTAL 215552

// ---------------------------------------------------------------- device scratch
__device__ __nv_bfloat16 g_A_hi[NWIN_ * 64 * 72];
__device__ __nv_bfloat16 g_A_lo[NWIN_ * 64 * 72];
__device__ __nv_bfloat16 g_Wp_hi[4 * 256 * 72];   // [chunk][n][72]
__device__ __nv_bfloat16 g_Wp_lo[4 * 256 * 72];
__device__ float         g_Asum[NWIN_ * 64];

// ---------------------------------------------------------------- helpers
__device__ __forceinline__ uint32_t smem_u32(const void* p) {
    uint32_t a;
    asm("{ .reg .u64 t; cvta.to.shared.u64 t, %1; cvt.u32.u64 %0, t; }" : "=r"(a) : "l"(p));
    return a;
}
__device__ __forceinline__ void cp16(uint32_t saddr, const void* g) {
    asm volatile("cp.async.cg.shared.global [%0], [%1], 16;" :: "r"(saddr), "l"(g) : "memory");
}
#define CP_COMMIT() asm volatile("cp.async.commit_group;" ::: "memory")
#define CP_WAIT0()  asm volatile("cp.async.wait_group 0;" ::: "memory")
#define CP_WAIT1()  asm volatile("cp.async.wait_group 1;" ::: "memory")

__device__ __forceinline__ void mma16816(float* d, const uint32_t* a, uint32_t b0, uint32_t b1) {
    asm volatile(
        "mma.sync.aligned.m16n8k16.row.col.f32.bf16.bf16.f32 "
        "{%0,%1,%2,%3}, {%4,%5,%6,%7}, {%8,%9}, {%0,%1,%2,%3};"
        : "+f"(d[0]), "+f"(d[1]), "+f"(d[2]), "+f"(d[3])
        : "r"(a[0]), "r"(a[1]), "r"(a[2]), "r"(a[3]), "r"(b0), "r"(b1));
}
__device__ __forceinline__ uint32_t pack_hi(float v0, float v1) {
    __nv_bfloat162 t; t.x = __float2bfloat16(v0); t.y = __float2bfloat16(v1);
    return *reinterpret_cast<uint32_t*>(&t);
}
__device__ __forceinline__ uint32_t pack_lo(float v0, float v1) {
    __nv_bfloat16 h0 = __float2bfloat16(v0), h1 = __float2bfloat16(v1);
    __nv_bfloat162 t;
    t.x = __float2bfloat16(v0 - __bfloat162float(h0));
    t.y = __float2bfloat16(v1 - __bfloat162float(h1));
    return *reinterpret_cast<uint32_t*>(&t);
}
// global token row for window w (0..255), token q (0..63), batch b
__device__ __forceinline__ int grow1(int b, int w, int q) {
    return ((b * 256 + (w >> 2) * 4 + (q >> 4)) * 64 + (w & 3) * 16 + (q & 15));
}

// ---------------------------------------------------------------- prologue 1:
// A_w = deg_w @ edge_w -> bf16 hi/lo row-major padded + rowsums
__global__ void __launch_bounds__(256)
pack_A_kernel(const float* __restrict__ edge, const float* __restrict__ deg) {
    __shared__ float dg[L_ * L_], eg[L_ * L_];
    const int w = blockIdx.x;
    for (int i = threadIdx.x; i < L_ * L_; i += 256) {
        dg[i] = deg[w * L_ * L_ + i];
        eg[i] = edge[w * L_ * L_ + i];
    }
    __syncthreads();
    const int p  = threadIdx.x >> 2;
    const int q0 = (threadIdx.x & 3) * 16;
    float acc[16];
#pragma unroll
    for (int j = 0; j < 16; j++) acc[j] = 0.f;
    for (int k = 0; k < L_; k++) {
        const float a = dg[p * L_ + k];
#pragma unroll
        for (int j = 0; j < 16; j++) acc[j] = fmaf(a, eg[k * L_ + q0 + j], acc[j]);
    }
    __nv_bfloat16* bh = g_A_hi + (size_t)w * 64 * 72 + p * 72;
    __nv_bfloat16* bl = g_A_lo + (size_t)w * 64 * 72 + p * 72;
    float rsum = 0.f;
#pragma unroll
    for (int j = 0; j < 16; j++) {
        rsum += acc[j];
        __nv_bfloat16 h = __float2bfloat16(acc[j]);
        bh[q0 + j] = h;
        bl[q0 + j] = __float2bfloat16(acc[j] - __bfloat162float(h));
    }
    rsum += __shfl_xor_sync(0xFFFFFFFFu, rsum, 1);
    rsum += __shfl_xor_sync(0xFFFFFFFFu, rsum, 2);
    if ((threadIdx.x & 3) == 0) g_Asum[w * 64 + p] = rsum;
}

// ---------------------------------------------------------------- prologue 2:
// Wp row-major fp32 [n][k] -> bf16 hi/lo [chunk][n][72]
__global__ void __launch_bounds__(256)
pack_Wp_kernel(const float* __restrict__ Wp) {
    const int n = blockIdx.x, k = threadIdx.x;
    const float v = Wp[n * 256 + k];
    const int idx = (k >> 6) * (256 * 72) + n * 72 + (k & 63);
    __nv_bfloat16 h = __float2bfloat16(v);
    g_Wp_hi[idx] = h;
    g_Wp_lo[idx] = __float2bfloat16(v - __bfloat162float(h));
}

// ---------------------------------------------------------------- main kernel
__global__ void __launch_bounds__(256, 1)
window_kernel(const float* __restrict__ x,
              const float* __restrict__ gamma,
              const float* __restrict__ beta,
              const float* __restrict__ bp,
              float* __restrict__ out) {
    extern __shared__ char sm[];
    const int tid  = threadIdx.x;
    const int warp = tid >> 5;
    const int lane = tid & 31;
    const int w    = blockIdx.x;
    const int b    = blockIdx.y;

    float* mu_s = (float*)(sm + SMALL);
    float* rs_s = (float*)(sm + SMALL + 256);

    // ---- stage A_w planes via cp.async (overlaps with LayerNorm) ----------
    {
        const uint32_t sA = smem_u32(sm) + A_HI;
        const char* gh = (const char*)(g_A_hi + (size_t)w * 64 * 72);
        const char* gl = (const char*)(g_A_lo + (size_t)w * 64 * 72);
        for (int i = tid; i < 576; i += 256) {           // 9216/16
            cp16(sA + i * 16, gh + i * 16);
            cp16(sA + (A_LO - A_HI) + i * 16, gl + i * 16);
        }
        CP_COMMIT();
    }

    // ---- LayerNorm stats: warp per token ----------------------------------
    for (int r = 0; r < 8; r++) {
        const int t = warp * 8 + r;
        const float* xr = x + (size_t)grow1(b, w, t) * 256;
        const float4 v0 = *(const float4*)(xr + lane * 4);
        const float4 v1 = *(const float4*)(xr + 128 + lane * 4);
        float s  = v0.x + v0.y + v0.z + v0.w + v1.x + v1.y + v1.z + v1.w;
        float s2 = v0.x*v0.x + v0.y*v0.y + v0.z*v0.z + v0.w*v0.w
                 + v1.x*v1.x + v1.y*v1.y + v1.z*v1.z + v1.w*v1.w;
#pragma unroll
        for (int o = 16; o > 0; o >>= 1) {
            s  += __shfl_xor_sync(0xFFFFFFFFu, s,  o);
            s2 += __shfl_xor_sync(0xFFFFFFFFu, s2, o);
        }
        if (lane == 0) {
            const float mean = s * (1.f / 256.f);
            mu_s[t] = mean;
            rs_s[t] = rsqrtf(s2 * (1.f / 256.f) - mean * mean + 1e-5f);
        }
    }
    __syncthreads();

    // ---- normalize + split + write xn_T[c][q] hi/lo -----------------------
    {
        const int c = tid;
        const float gc = gamma[c], bc = beta[c];
        char* ph = sm + XN_HI + c * XN_STRIDE;
        char* pl = sm + XN_LO + c * XN_STRIDE;
        for (int qp = 0; qp < 32; qp++) {
            const int q0 = 2 * qp;
            const float x0 = x[(size_t)grow1(b, w, q0) * 256 + c];
            const float x1 = x[(size_t)grow1(b, w, q0 + 1) * 256 + c];
            const float v0 = (x0 - mu_s[q0]) * rs_s[q0] * gc + bc;
            const float v1 = (x1 - mu_s[q0 + 1]) * rs_s[q0 + 1] * gc + bc;
            *(uint32_t*)(ph + qp * 4) = pack_hi(v0, v1);
            *(uint32_t*)(pl + qp * 4) = pack_lo(v0, v1);
        }
    }
    CP_WAIT0();          // A_w staged
    __syncthreads();

    // warp tile: 32 (m) x 64 (n)
    const int wm = (warp & 1) * 32;
    const int wn = (warp >> 1) * 64;
    const int r4 = lane >> 2;          // 0..7
    const int j4 = (lane & 3) * 4;     // byte offset of k-pair

    float D[2][8][4];
#pragma unroll
    for (int mb = 0; mb < 2; mb++)
#pragma unroll
        for (int nb = 0; nb < 8; nb++)
#pragma unroll
            for (int v = 0; v < 4; v++) D[mb][nb][v] = 0.f;

    // ---- GEMM1: t = A_w @ xn  (K=64, 4 ksteps) ----------------------------
#pragma unroll
    for (int ks = 0; ks < 4; ks++) {
        uint32_t Ah[2][4], Al[2][4];
#pragma unroll
        for (int mb = 0; mb < 2; mb++) {
            const int aoff = (wm + mb * 16 + r4) * A_STRIDE + ks * 32 + j4;
            Ah[mb][0] = *(const uint32_t*)(sm + A_HI + aoff);
            Ah[mb][1] = *(const uint32_t*)(sm + A_HI + aoff + 8 * A_STRIDE);
            Ah[mb][2] = *(const uint32_t*)(sm + A_HI + aoff + 16);
            Ah[mb][3] = *(const uint32_t*)(sm + A_HI + aoff + 8 * A_STRIDE + 16);
            Al[mb][0] = *(const uint32_t*)(sm + A_LO + aoff);
            Al[mb][1] = *(const uint32_t*)(sm + A_LO + aoff + 8 * A_STRIDE);
            Al[mb][2] = *(const uint32_t*)(sm + A_LO + aoff + 16);
            Al[mb][3] = *(const uint32_t*)(sm + A_LO + aoff + 8 * A_STRIDE + 16);
        }
#pragma unroll
        for (int nb = 0; nb < 8; nb++) {
            const int boff = (wn + nb * 8 + r4) * XN_STRIDE + ks * 32 + j4;
            const uint32_t bh0 = *(const uint32_t*)(sm + XN_HI + boff);
            const uint32_t bh1 = *(const uint32_t*)(sm + XN_HI + boff + 16);
            const uint32_t bl0 = *(const uint32_t*)(sm + XN_LO + boff);
            const uint32_t bl1 = *(const uint32_t*)(sm + XN_LO + boff + 16);
#pragma unroll
            for (int mb = 0; mb < 2; mb++) {
                mma16816(D[mb][nb], Ah[mb], bh0, bh1);
                mma16816(D[mb][nb], Ah[mb], bl0, bl1);
                mma16816(D[mb][nb], Al[mb], bh0, bh1);
            }
        }
    }

    // ---- store t as bf16 hi/lo, row-major [m][k=ch] -----------------------
#pragma unroll
    for (int mb = 0; mb < 2; mb++) {
#pragma unroll
        for (int nb = 0; nb < 8; nb++) {
            const int m0 = wm + mb * 16 + r4;
            const int n0 = wn + nb * 8 + (lane & 3) * 2;
            float* d = D[mb][nb];
            *(uint32_t*)(sm + T_HI + m0 * T_STRIDE + n0 * 2)       = pack_hi(d[0], d[1]);
            *(uint32_t*)(sm + T_LO + m0 * T_STRIDE + n0 * 2)       = pack_lo(d[0], d[1]);
            *(uint32_t*)(sm + T_HI + (m0 + 8) * T_STRIDE + n0 * 2) = pack_hi(d[2], d[3]);
            *(uint32_t*)(sm + T_LO + (m0 + 8) * T_STRIDE + n0 * 2) = pack_lo(d[2], d[3]);
        }
    }
    __syncthreads();   // t visible; xn/A regions now dead

    // ---- prefetch Wp chunks 0,1 (double-buffered) -------------------------
    {
        const uint32_t s0 = smem_u32(sm) + BUF0;
        for (int i = tid; i < 2304; i += 256) {          // 36864/16
            cp16(s0 + i * 16, (const char*)g_Wp_hi + i * 16);
            cp16(s0 + WP_PLANE + i * 16, (const char*)g_Wp_lo + i * 16);
        }
        CP_COMMIT();
        const uint32_t s1 = smem_u32(sm) + BUF1;
        for (int i = tid; i < 2304; i += 256) {
            cp16(s1 + i * 16, (const char*)g_Wp_hi + 36864 + i * 16);
            cp16(s1 + WP_PLANE + i * 16, (const char*)g_Wp_lo + 36864 + i * 16);
        }
        CP_COMMIT();
    }

    // zero accumulators for GEMM2
#pragma unroll
    for (int mb = 0; mb < 2; mb++)
#pragma unroll
        for (int nb = 0; nb < 8; nb++)
#pragma unroll
            for (int v = 0; v < 4; v++) D[mb][nb][v] = 0.f;

    // ---- GEMM2: out = t @ Wp^T  (K=256, 4 chunks of 64) -------------------
    for (int ch = 0; ch < 4; ch++) {
        if (ch < 3) { CP_WAIT1(); } else { CP_WAIT0(); }
        __syncthreads();
        const int bufo = (ch & 1) ? BUF1 : BUF0;
#pragma unroll
        for (int ks = 0; ks < 4; ks++) {
            uint32_t Ah[2][4], Al[2][4];
#pragma unroll
            for (int mb = 0; mb < 2; mb++) {
                const int aoff = (wm + mb * 16 + r4) * T_STRIDE + ch * 128 + ks * 32 + j4;
                Ah[mb][0] = *(const uint32_t*)(sm + T_HI + aoff);
                Ah[mb][1] = *(const uint32_t*)(sm + T_HI + aoff + 8 * T_STRIDE);
                Ah[mb][2] = *(const uint32_t*)(sm + T_HI + aoff + 16);
                Ah[mb][3] = *(const uint32_t*)(sm + T_HI + aoff + 8 * T_STRIDE + 16);
                Al[mb][0] = *(const uint32_t*)(sm + T_LO + aoff);
                Al[mb][1] = *(const uint32_t*)(sm + T_LO + aoff + 8 * T_STRIDE);
                Al[mb][2] = *(const uint32_t*)(sm + T_LO + aoff + 16);
                Al[mb][3] = *(const uint32_t*)(sm + T_LO + aoff + 8 * T_STRIDE + 16);
            }
#pragma unroll
            for (int nb = 0; nb < 8; nb++) {
                const int boff = bufo + (wn + nb * 8 + r4) * WP_STRIDE + ks * 32 + j4;
                const uint32_t bh0 = *(const uint32_t*)(sm + boff);
                const uint32_t bh1 = *(const uint32_t*)(sm + boff + 16);
                const uint32_t bl0 = *(const uint32_t*)(sm + boff + WP_PLANE);
                const uint32_t bl1 = *(const uint32_t*)(sm + boff + WP_PLANE + 16);
#pragma unroll
                for (int mb = 0; mb < 2; mb++) {
                    mma16816(D[mb][nb], Ah[mb], bh0, bh1);
                    mma16816(D[mb][nb], Ah[mb], bl0, bl1);
                    mma16816(D[mb][nb], Al[mb], bh0, bh1);
                }
            }
        }
        __syncthreads();   // all warps done with this buffer
        if (ch + 2 < 4) {  // refill this buffer with chunk ch+2
            const uint32_t sb = smem_u32(sm) + bufo;
            const char* gh = (const char*)g_Wp_hi + (ch + 2) * 36864;
            const char* gl = (const char*)g_Wp_lo + (ch + 2) * 36864;
            for (int i = tid; i < 2304; i += 256) {
                cp16(sb + i * 16, gh + i * 16);
                cp16(sb + WP_PLANE + i * 16, gl + i * 16);
            }
            CP_COMMIT();
        }
    }

    // ---- epilogue: out = D + rowsum(A)[m]*bp[n], window-reverse -----------
#pragma unroll
    for (int mb = 0; mb < 2; mb++) {
        const int m0 = wm + mb * 16 + r4;
        const int rowA = grow1(b, w, m0);
        const int rowB = grow1(b, w, m0 + 8);
        const float sA = g_Asum[w * 64 + m0];
        const float sB = g_Asum[w * 64 + m0 + 8];
#pragma unroll
        for (int nb = 0; nb < 8; nb++) {
            const int n0 = wn + nb * 8 + (lane & 3) * 2;
            const float2 bpv = *(const float2*)(bp + n0);
            float* d = D[mb][nb];
            float2 z0, z1;
            z0.x = d[0] + sA * bpv.x;  z0.y = d[1] + sA * bpv.y;
            z1.x = d[2] + sB * bpv.x;  z1.y = d[3] + sB * bpv.y;
            *(float2*)(out + (size_t)rowA * 256 + n0) = z0;
            *(float2*)(out + (size_t)rowB * 256 + n0) = z1;
        }
    }
}

// ---------------------------------------------------------------- launch
extern "C" void kernel_launch(void* const* d_in, const int* in_sizes, int n_in,
                              void* d_out, int out_size) {
    (void)in_sizes; (void)n_in; (void)out_size;
    const float* x     = (const float*)d_in[0];
    const float* gamma = (const float*)d_in[1];
    const float* beta  = (const float*)d_in[2];
    const float* Wp    = (const float*)d_in[3];
    const float* bp    = (const float*)d_in[4];
    const float* edge  = (const float*)d_in[5];
    const float* deg   = (const float*)d_in[6];
    float* out = (float*)d_out;

    pack_A_kernel<<<NWIN_, 256>>>(edge, deg);
    pack_Wp_kernel<<<256, 256>>>(Wp);

    cudaFuncSetAttribute(window_kernel, cudaFuncAttributeMaxDynamicSharedMemorySize, SMEM_TOTAL);
    window_kernel<<<dim3(NWIN_, B_), 256, SMEM_TOTAL>>>(x, gamma, beta, bp, out);
}

// round 10
// speedup vs baseline: 3.3583x; 1.7926x over previous
#include <cuda_runtime.h>
#include <cuda_fp16.h>
#include <cstdint>

// ---------------------------------------------------------------- constants
#define B_     8
#define L_     64
#define NWIN_  256

// strides (bytes); stride/4 mod 32 == 4 -> conflict-free fragment rows
#define XN_STRIDE  144   // 64 fp16 used (128B) + pad
#define A_STRIDE   144   // global A row stride (72 fp16)
#define WP_STRIDE  80    // 32 fp16 used (64B) + pad ; 20 mod 32 pattern ok
#define T_STRIDE   528   // 256 fp16 used (512B) + pad

// smem layout (bytes)
#define T_HI    0        // 64*528 = 33792
#define T_LO    33792
#define XN_OFF  67584    // 256*144 = 36864 (dead after GEMM1)
#define BUF0    67584    // Wp chunk buf0: 256*80 = 20480
#define BUF1    88064    // buf1: 20480 -> ends 108544
#define SMALL   108544   // mu @+0 (256B), rs @+256 (256B)
#define SMEM_TOTAL 109056

// ---------------------------------------------------------------- device scratch
__device__ __half g_A_hi[NWIN_ * 64 * 72];   // [w][row][72]
__device__ __half g_A_lo[NWIN_ * 64 * 72];
__device__ __half g_Wp[8 * 256 * 40];        // [chunk k=32][n][40]
__device__ float  g_Asum[NWIN_ * 64];

// ---------------------------------------------------------------- helpers
__device__ __forceinline__ uint32_t smem_u32(const void* p) {
    uint32_t a;
    asm("{ .reg .u64 t; cvta.to.shared.u64 t, %1; cvt.u32.u64 %0, t; }" : "=r"(a) : "l"(p));
    return a;
}
__device__ __forceinline__ void cp16(uint32_t saddr, const void* g) {
    asm volatile("cp.async.cg.shared.global [%0], [%1], 16;" :: "r"(saddr), "l"(g) : "memory");
}
#define CP_COMMIT() asm volatile("cp.async.commit_group;" ::: "memory")
#define CP_WAIT0()  asm volatile("cp.async.wait_group 0;" ::: "memory")
#define CP_WAIT1()  asm volatile("cp.async.wait_group 1;" ::: "memory")

__device__ __forceinline__ void mma16816(float* d, const uint32_t* a, uint32_t b0, uint32_t b1) {
    asm volatile(
        "mma.sync.aligned.m16n8k16.row.col.f32.f16.f16.f32 "
        "{%0,%1,%2,%3}, {%4,%5,%6,%7}, {%8,%9}, {%0,%1,%2,%3};"
        : "+f"(d[0]), "+f"(d[1]), "+f"(d[2]), "+f"(d[3])
        : "r"(a[0]), "r"(a[1]), "r"(a[2]), "r"(a[3]), "r"(b0), "r"(b1));
}
__device__ __forceinline__ uint32_t pack2h(float v0, float v1) {
    __half2 t; t.x = __float2half_rn(v0); t.y = __float2half_rn(v1);
    return *reinterpret_cast<uint32_t*>(&t);
}
__device__ __forceinline__ uint32_t pack2l(float v0, float v1) {
    __half h0 = __float2half_rn(v0), h1 = __float2half_rn(v1);
    __half2 t;
    t.x = __float2half_rn(v0 - __half2float(h0));
    t.y = __float2half_rn(v1 - __half2float(h1));
    return *reinterpret_cast<uint32_t*>(&t);
}
// global token row for window w (0..255), token q (0..63), batch b
__device__ __forceinline__ int grow1(int b, int w, int q) {
    return ((b * 256 + (w >> 2) * 4 + (q >> 4)) * 64 + (w & 3) * 16 + (q & 15));
}

// ---------------------------------------------------------------- prologue 1:
// A_w = deg_w @ edge_w -> fp16 hi/lo padded rows + rowsums.
// 4 CTAs per window (16 rows each) for latency hiding.
__global__ void __launch_bounds__(256)
pack_A_kernel(const float* __restrict__ edge, const float* __restrict__ deg) {
    __shared__ float eg[64 * 64];
    __shared__ float dgp[16 * 64];
    const int w = blockIdx.x >> 2, part = blockIdx.x & 3;
    const int tid = threadIdx.x;
    {
        const float4* eG = (const float4*)(edge + (size_t)w * 4096);
        float4* eS = (float4*)eg;
        for (int i = tid; i < 1024; i += 256) eS[i] = eG[i];
        const float4* dG = (const float4*)(deg + (size_t)w * 4096 + part * 1024);
        float4* dS = (float4*)dgp;
        if (tid < 256) dS[tid] = dG[tid];
    }
    __syncthreads();
    const int row = tid >> 4;             // 0..15
    const int q0  = (tid & 15) * 4;       // 0..60
    float a0 = 0.f, a1 = 0.f, a2 = 0.f, a3 = 0.f;
#pragma unroll 8
    for (int k = 0; k < 64; k++) {
        const float a = dgp[row * 64 + k];
        const float4 e = *(const float4*)&eg[k * 64 + q0];
        a0 = fmaf(a, e.x, a0); a1 = fmaf(a, e.y, a1);
        a2 = fmaf(a, e.z, a2); a3 = fmaf(a, e.w, a3);
    }
    const int p = part * 16 + row;
    __half* bh = g_A_hi + (size_t)w * 64 * 72 + p * 72 + q0;
    __half* bl = g_A_lo + (size_t)w * 64 * 72 + p * 72 + q0;
    const float v[4] = {a0, a1, a2, a3};
#pragma unroll
    for (int j = 0; j < 4; j++) {
        __half h = __float2half_rn(v[j]);
        bh[j] = h;
        bl[j] = __float2half_rn(v[j] - __half2float(h));
    }
    float rsum = a0 + a1 + a2 + a3;
#pragma unroll
    for (int o = 1; o < 16; o <<= 1) rsum += __shfl_xor_sync(0xFFFFFFFFu, rsum, o);
    if ((tid & 15) == 0) g_Asum[w * 64 + p] = rsum;
}

// ---------------------------------------------------------------- prologue 2:
// Wp row-major fp32 [n][k] -> single fp16 plane [chunk k=32][n][40]
__global__ void __launch_bounds__(256)
pack_Wp_kernel(const float* __restrict__ Wp) {
    const int n = blockIdx.x, k = threadIdx.x;
    const float v = Wp[n * 256 + k];
    g_Wp[(k >> 5) * (256 * 40) + n * 40 + (k & 31)] = __float2half_rn(v);
}

// ---------------------------------------------------------------- main kernel
__global__ void __launch_bounds__(256, 2)
window_kernel(const float* __restrict__ x,
              const float* __restrict__ gamma,
              const float* __restrict__ beta,
              const float* __restrict__ bp,
              float* __restrict__ out) {
    extern __shared__ char sm[];
    const int tid  = threadIdx.x;
    const int warp = tid >> 5;
    const int lane = tid & 31;
    const int w    = blockIdx.x;
    const int b    = blockIdx.y;

    float* mu_s = (float*)(sm + SMALL);
    float* rs_s = (float*)(sm + SMALL + 256);

    // ---- LayerNorm stats: warp per token ----------------------------------
    for (int r = 0; r < 8; r++) {
        const int t = warp * 8 + r;
        const float* xr = x + (size_t)grow1(b, w, t) * 256;
        const float4 v0 = *(const float4*)(xr + lane * 4);
        const float4 v1 = *(const float4*)(xr + 128 + lane * 4);
        float s  = v0.x + v0.y + v0.z + v0.w + v1.x + v1.y + v1.z + v1.w;
        float s2 = v0.x*v0.x + v0.y*v0.y + v0.z*v0.z + v0.w*v0.w
                 + v1.x*v1.x + v1.y*v1.y + v1.z*v1.z + v1.w*v1.w;
#pragma unroll
        for (int o = 16; o > 0; o >>= 1) {
            s  += __shfl_xor_sync(0xFFFFFFFFu, s,  o);
            s2 += __shfl_xor_sync(0xFFFFFFFFu, s2, o);
        }
        if (lane == 0) {
            const float mean = s * (1.f / 256.f);
            mu_s[t] = mean;
            rs_s[t] = rsqrtf(s2 * (1.f / 256.f) - mean * mean + 1e-5f);
        }
    }
    __syncthreads();

    // ---- normalize + write xn_T[c][q] single fp16 plane -------------------
    {
        const int c = tid;
        const float gc = gamma[c], bc = beta[c];
        char* ph = sm + XN_OFF + c * XN_STRIDE;
#pragma unroll 4
        for (int qp = 0; qp < 32; qp++) {
            const int q0 = 2 * qp;
            const float x0 = x[(size_t)grow1(b, w, q0) * 256 + c];
            const float x1 = x[(size_t)grow1(b, w, q0 + 1) * 256 + c];
            const float v0 = (x0 - mu_s[q0]) * rs_s[q0] * gc + bc;
            const float v1 = (x1 - mu_s[q0 + 1]) * rs_s[q0 + 1] * gc + bc;
            *(uint32_t*)(ph + qp * 4) = pack2h(v0, v1);
        }
    }
    __syncthreads();

    // warp tile: 32 (m) x 64 (n)
    const int wm = (warp & 1) * 32;
    const int wn = (warp >> 1) * 64;
    const int r4 = lane >> 2;          // 0..7
    const int j4 = (lane & 3) * 4;     // byte offset of k-pair

    float D[2][8][4];
#pragma unroll
    for (int mb = 0; mb < 2; mb++)
#pragma unroll
        for (int nb = 0; nb < 8; nb++)
#pragma unroll
            for (int v = 0; v < 4; v++) D[mb][nb][v] = 0.f;

    // ---- GEMM1: t = A_w @ xn  (K=64, A hi/lo from L2, xn single) ----------
    {
        const char* gAh = (const char*)(g_A_hi + (size_t)w * 64 * 72);
        const char* gAl = (const char*)(g_A_lo + (size_t)w * 64 * 72);
#pragma unroll
        for (int ks = 0; ks < 4; ks++) {
            uint32_t Ah[2][4], Al[2][4];
#pragma unroll
            for (int mb = 0; mb < 2; mb++) {
                const int aoff = (wm + mb * 16 + r4) * A_STRIDE + ks * 32 + j4;
                Ah[mb][0] = *(const uint32_t*)(gAh + aoff);
                Ah[mb][1] = *(const uint32_t*)(gAh + aoff + 8 * A_STRIDE);
                Ah[mb][2] = *(const uint32_t*)(gAh + aoff + 16);
                Ah[mb][3] = *(const uint32_t*)(gAh + aoff + 8 * A_STRIDE + 16);
                Al[mb][0] = *(const uint32_t*)(gAl + aoff);
                Al[mb][1] = *(const uint32_t*)(gAl + aoff + 8 * A_STRIDE);
                Al[mb][2] = *(const uint32_t*)(gAl + aoff + 16);
                Al[mb][3] = *(const uint32_t*)(gAl + aoff + 8 * A_STRIDE + 16);
            }
#pragma unroll
            for (int nb = 0; nb < 8; nb++) {
                const int boff = XN_OFF + (wn + nb * 8 + r4) * XN_STRIDE + ks * 32 + j4;
                const uint32_t b0 = *(const uint32_t*)(sm + boff);
                const uint32_t b1 = *(const uint32_t*)(sm + boff + 16);
#pragma unroll
                for (int mb = 0; mb < 2; mb++) {
                    mma16816(D[mb][nb], Ah[mb], b0, b1);
                    mma16816(D[mb][nb], Al[mb], b0, b1);
                }
            }
        }
    }

    // ---- store t as fp16 hi/lo, row-major [m][k] --------------------------
#pragma unroll
    for (int mb = 0; mb < 2; mb++) {
#pragma unroll
        for (int nb = 0; nb < 8; nb++) {
            const int m0 = wm + mb * 16 + r4;
            const int n0 = wn + nb * 8 + (lane & 3) * 2;
            float* d = D[mb][nb];
            *(uint32_t*)(sm + T_HI + m0 * T_STRIDE + n0 * 2)       = pack2h(d[0], d[1]);
            *(uint32_t*)(sm + T_LO + m0 * T_STRIDE + n0 * 2)       = pack2l(d[0], d[1]);
            *(uint32_t*)(sm + T_HI + (m0 + 8) * T_STRIDE + n0 * 2) = pack2h(d[2], d[3]);
            *(uint32_t*)(sm + T_LO + (m0 + 8) * T_STRIDE + n0 * 2) = pack2l(d[2], d[3]);
        }
    }
    __syncthreads();   // t visible; xn region now dead -> Wp buffers

    // ---- prefetch Wp chunks 0,1 (20480 B each) ----------------------------
    {
        const uint32_t s0 = smem_u32(sm) + BUF0;
        const uint32_t s1 = smem_u32(sm) + BUF1;
        const char* g0 = (const char*)g_Wp;
        for (int i = tid; i < 1280; i += 256) cp16(s0 + i * 16, g0 + i * 16);
        CP_COMMIT();
        for (int i = tid; i < 1280; i += 256) cp16(s1 + i * 16, g0 + 20480 + i * 16);
        CP_COMMIT();
    }

    // zero accumulators for GEMM2
#pragma unroll
    for (int mb = 0; mb < 2; mb++)
#pragma unroll
        for (int nb = 0; nb < 8; nb++)
#pragma unroll
            for (int v = 0; v < 4; v++) D[mb][nb][v] = 0.f;

    // ---- GEMM2: out = t @ Wp^T  (K=256, 8 chunks of 32, double-buffered) --
    for (int ch = 0; ch < 8; ch++) {
        if (ch < 7) { CP_WAIT1(); } else { CP_WAIT0(); }
        __syncthreads();
        const int bufo = (ch & 1) ? BUF1 : BUF0;
#pragma unroll
        for (int ks = 0; ks < 2; ks++) {
            uint32_t Ah[2][4], Al[2][4];
#pragma unroll
            for (int mb = 0; mb < 2; mb++) {
                const int aoff = (wm + mb * 16 + r4) * T_STRIDE + ch * 64 + ks * 32 + j4;
                Ah[mb][0] = *(const uint32_t*)(sm + T_HI + aoff);
                Ah[mb][1] = *(const uint32_t*)(sm + T_HI + aoff + 8 * T_STRIDE);
                Ah[mb][2] = *(const uint32_t*)(sm + T_HI + aoff + 16);
                Ah[mb][3] = *(const uint32_t*)(sm + T_HI + aoff + 8 * T_STRIDE + 16);
                Al[mb][0] = *(const uint32_t*)(sm + T_LO + aoff);
                Al[mb][1] = *(const uint32_t*)(sm + T_LO + aoff + 8 * T_STRIDE);
                Al[mb][2] = *(const uint32_t*)(sm + T_LO + aoff + 16);
                Al[mb][3] = *(const uint32_t*)(sm + T_LO + aoff + 8 * T_STRIDE + 16);
            }
#pragma unroll
            for (int nb = 0; nb < 8; nb++) {
                const int boff = bufo + (wn + nb * 8 + r4) * WP_STRIDE + ks * 32 + j4;
                const uint32_t b0 = *(const uint32_t*)(sm + boff);
                const uint32_t b1 = *(const uint32_t*)(sm + boff + 16);
#pragma unroll
                for (int mb = 0; mb < 2; mb++) {
                    mma16816(D[mb][nb], Ah[mb], b0, b1);
                    mma16816(D[mb][nb], Al[mb], b0, b1);
                }
            }
        }
        __syncthreads();   // all warps done with this buffer
        if (ch < 6) {      // refill with chunk ch+2
            const uint32_t sb = smem_u32(sm) + bufo;
            const char* g = (const char*)g_Wp + (ch + 2) * 20480;
            for (int i = tid; i < 1280; i += 256) cp16(sb + i * 16, g + i * 16);
            CP_COMMIT();
        }
    }

    // ---- epilogue: out = D + rowsum(A)[m]*bp[n], window-reverse -----------
#pragma unroll
    for (int mb = 0; mb < 2; mb++) {
        const int m0 = wm + mb * 16 + r4;
        const int rowA = grow1(b, w, m0);
        const int rowB = grow1(b, w, m0 + 8);
        const float sA = g_Asum[w * 64 + m0];
        const float sB = g_Asum[w * 64 + m0 + 8];
#pragma unroll
        for (int nb = 0; nb < 8; nb++) {
            const int n0 = wn + nb * 8 + (lane & 3) * 2;
            const float2 bpv = *(const float2*)(bp + n0);
            float* d = D[mb][nb];
            float2 z0, z1;
            z0.x = d[0] + sA * bpv.x;  z0.y = d[1] + sA * bpv.y;
            z1.x = d[2] + sB * bpv.x;  z1.y = d[3] + sB * bpv.y;
            *(float2*)(out + (size_t)rowA * 256 + n0) = z0;
            *(float2*)(out + (size_t)rowB * 256 + n0) = z1;
        }
    }
}

// ---------------------------------------------------------------- launch
extern "C" void kernel_launch(void* const* d_in, const int* in_sizes, int n_in,
                              void* d_out, int out_size) {
    (void)in_sizes; (void)n_in; (void)out_size;
    const float* x     = (const float*)d_in[0];
    const float* gamma = (const float*)d_in[1];
    const float* beta  = (const float*)d_in[2];
    const float* Wp    = (const float*)d_in[3];
    const float* bp    = (const float*)d_in[4];
    const float* edge  = (const float*)d_in[5];
    const float* deg   = (const float*)d_in[6];
    float* out = (float*)d_out;

    pack_A_kernel<<<NWIN_ * 4, 256>>>(edge, deg);
    pack_Wp_kernel<<<256, 256>>>(Wp);

    cudaFuncSetAttribute(window_kernel, cudaFuncAttributeMaxDynamicSharedMemorySize, SMEM_TOTAL);
    window_kernel<<<dim3(NWIN_, B_), 256, SMEM_TOTAL>>>(x, gamma, beta, bp, out);
}